// round 2
// baseline (speedup 1.0000x reference)
#include <cuda_runtime.h>
#include <cuda_bf16.h>

// ---------------------------------------------------------------------------
// Exact 5x5 median filter, fp32, symmetric (reflect) padding.
// Strategy:
//   * vertical sliding strip per thread (16 outputs): row sorts amortized 1/pixel
//   * doubly-sorted matrix pruning: median(25) = rank-7 of 13 candidates
//   * Batcher merges of candidate chains + split-formula selection
// Bottleneck: FMNMX (alu pipe). ~140 min/max per pixel.
// ---------------------------------------------------------------------------

#define CEX(a, b)                         \
    do {                                  \
        float _mn = fminf((a), (b));      \
        (b) = fmaxf((a), (b));            \
        (a) = _mn;                        \
    } while (0)

// Optimal 9-comparator sorting network for 5 elements (Knuth).
__device__ __forceinline__ void sort5r(float& v0, float& v1, float& v2, float& v3, float& v4) {
    CEX(v0, v1); CEX(v3, v4); CEX(v2, v4); CEX(v2, v3); CEX(v0, v3);
    CEX(v0, v2); CEX(v1, v4); CEX(v1, v3); CEX(v1, v2);
}

// symmetric reflect for pad<=2:  -1 -> 0, -2 -> 1, N -> N-1, N+1 -> N-2
__device__ __forceinline__ int refl(int i, int n) {
    i = (i < 0) ? (-1 - i) : i;
    i = (i >= n) ? (2 * n - 1 - i) : i;
    return i;
}

constexpr int IMG_H  = 512;
constexpr int IMG_W  = 512;
constexpr int PLANES = 16 * 3;          // B*C
constexpr int TROWS  = 16;              // outputs per thread (vertical strip)
constexpr int STRIPS = IMG_H / TROWS;   // 32

__global__ void __launch_bounds__(256)
median5x5_kernel(const float* __restrict__ src, float* __restrict__ dst) {
    const int tid   = blockIdx.x * blockDim.x + threadIdx.x;
    const int x     = tid & (IMG_W - 1);
    const int rest  = tid >> 9;                 // / 512
    const int strip = rest & (STRIPS - 1);      // % 32
    const int plane = rest >> 5;                // / 32
    if (plane >= PLANES) return;

    const float* s = src + (size_t)plane * IMG_H * IMG_W;
    float*       d = dst + (size_t)plane * IMG_H * IMG_W;

    const int xm2 = refl(x - 2, IMG_W);
    const int xm1 = refl(x - 1, IMG_W);
    const int xp1 = refl(x + 1, IMG_W);
    const int xp2 = refl(x + 2, IMG_W);
    const int y0  = strip * TROWS;

    // Ring of 5 sorted horizontal windows (registers; all indices static
    // thanks to full unroll).
    float r[5][5];

    #pragma unroll
    for (int i = 0; i < 4; i++) {
        const int yy = refl(y0 - 2 + i, IMG_H);
        const float* row = s + yy * IMG_W;
        r[i][0] = __ldg(row + xm2);
        r[i][1] = __ldg(row + xm1);
        r[i][2] = __ldg(row + x);
        r[i][3] = __ldg(row + xp1);
        r[i][4] = __ldg(row + xp2);
        sort5r(r[i][0], r[i][1], r[i][2], r[i][3], r[i][4]);
    }

    #pragma unroll
    for (int t = 0; t < TROWS; t++) {
        const int slot = (t + 4) % 5;   // compile-time constant per unrolled iter
        {
            const int yy = refl(y0 + t + 2, IMG_H);
            const float* row = s + yy * IMG_W;
            r[slot][0] = __ldg(row + xm2);
            r[slot][1] = __ldg(row + xm1);
            r[slot][2] = __ldg(row + x);
            r[slot][3] = __ldg(row + xp1);
            r[slot][4] = __ldg(row + xp2);
            sort5r(r[slot][0], r[slot][1], r[slot][2], r[slot][3], r[slot][4]);
        }

        // ---- column sorts -> doubly sorted 5x5 matrix -------------------
        // (window = all 5 ring slots; row order is irrelevant to the median)
        float a0 = r[0][0], a1 = r[1][0], a2 = r[2][0], a3 = r[3][0], a4 = r[4][0];
        float b0 = r[0][1], b1 = r[1][1], b2 = r[2][1], b3 = r[3][1], b4 = r[4][1];
        float c0 = r[0][2], c1 = r[1][2], c2 = r[2][2], c3 = r[3][2], c4 = r[4][2];
        float d0 = r[0][3], d1 = r[1][3], d2 = r[2][3], d3 = r[3][3], d4 = r[4][3];
        float e0 = r[0][4], e1 = r[1][4], e2 = r[2][4], e3 = r[3][4], e4 = r[4][4];
        sort5r(a0, a1, a2, a3, a4);
        sort5r(b0, b1, b2, b3, b4);
        sort5r(c0, c1, c2, c3, c4);
        sort5r(d0, d1, d2, d3, d4);
        sort5r(e0, e1, e2, e3, e4);
        // unused order statistics (a0..a2, b0..b1, c0, c4?, d3..d4, e2..e4, ...)
        // are dead and eliminated by the compiler.
        (void)a0; (void)a1; (void)a2; (void)b0; (void)b1; (void)c0; (void)c4;
        (void)d3; (void)d4; (void)e2; (void)e3; (void)e4;

        // 13 median candidates in 5 sorted chains (row chains of the
        // doubly-sorted matrix):
        //   R1 = (d0, e0)        R2 = (c1, d1, e1)      R3 = (b2, c2, d2)
        //   R4 = (a3, b3, c3)    R5 = (a4, b4)
        // median(25) = rank-7 of these 13.

        // U = batcher_merge(R1(2), R2(3)) -> sorted 5
        float s0 = fminf(d0, c1), t0 = fmaxf(d0, c1);
        float v1 = fminf(t0, e1), v2 = fmaxf(t0, e1);
        float w0 = fminf(e0, d1), w1 = fmaxf(e0, d1);
        float U0 = s0;
        float U1 = fminf(v1, w0), U2 = fmaxf(v1, w0);
        float U3 = fminf(v2, w1), U4 = fmaxf(v2, w1);

        // V = batcher_merge(R4(3), R5(2)) -> sorted 5
        float m0 = fminf(a3, a4), h0 = fmaxf(a3, a4);
        float o1 = fminf(h0, c3), o2 = fmaxf(h0, c3);
        float p0 = fminf(b3, b4), p1 = fmaxf(b3, b4);
        float V0 = m0;
        float V1 = fminf(o1, p0), V2 = fmaxf(o1, p0);
        float V3 = fminf(o2, p1), V4 = fmaxf(o2, p1);

        // W = batcher_merge(U(5), R3(3)) -> sorted 8 (only W1..W6 needed)
        //   odd lanes: merge((U0,U2,U4), (b2,d2))
        float mm  = fminf(U0, b2), hh  = fmaxf(U0, b2);
        float oo1 = fminf(hh, U4), oo2 = fmaxf(hh, U4);
        float qq0 = fminf(U2, d2), qq1 = fmaxf(U2, d2);
        float O1 = fminf(oo1, qq0), O2 = fmaxf(oo1, qq0);
        float O3 = fminf(oo2, qq1), O4 = fmaxf(oo2, qq1);
        (void)mm; (void)O4;  // W0 / W7 are dead
        //   even lanes: merge((U1,U3), (c2))
        float m2 = fminf(U1, c2), h2 = fmaxf(U1, c2);
        float E0 = m2;
        float E1 = fminf(h2, U3), E2 = fmaxf(h2, U3);
        //   combine
        float W1 = fminf(O1, E0), W2 = fmaxf(O1, E0);
        float W3 = fminf(O2, E1), W4 = fmaxf(O2, E1);
        float W5 = fminf(O3, E2), W6 = fmaxf(O3, E2);

        // rank-7 of union(W sorted 8, V sorted 5):
        //   min over i+j=7 of max(W[i-1], V[j-1])
        float med = W6;
        med = fminf(med, fmaxf(W1, V4));
        med = fminf(med, fmaxf(W2, V3));
        med = fminf(med, fmaxf(W3, V2));
        med = fminf(med, fmaxf(W4, V1));
        med = fminf(med, fmaxf(W5, V0));

        d[(y0 + t) * IMG_W + x] = med;
    }
}

extern "C" void kernel_launch(void* const* d_in, const int* in_sizes, int n_in,
                              void* d_out, int out_size) {
    (void)in_sizes; (void)n_in; (void)out_size;
    const float* src = (const float*)d_in[0];
    float*       dst = (float*)d_out;

    const int total_threads = PLANES * IMG_W * STRIPS;   // 786432
    const int block = 256;
    const int grid  = total_threads / block;             // 3072
    median5x5_kernel<<<grid, block>>>(src, dst);
}

// round 5
// speedup vs baseline: 1.6657x; 1.6657x over previous
#include <cuda_runtime.h>
#include <cuda_fp16.h>

// ---------------------------------------------------------------------------
// Exact-rank 5x5 median filter, fp32 in/out, symmetric (reflect) padding.
//   * comparator network evaluated in packed fp16 (HMNMX2): 2 planes/thread,
//     one instruction = two comparisons. Median commutes with the monotone
//     fp16 rounding, so the result is exactly fp16(true_median).
//   * x4096 pre-scale keeps all magnitudes in fp16 normal range (then /4096).
//   * vertical sliding strip per thread: row sorts amortized 1/pixel
//   * doubly-sorted matrix pruning: median(25) = rank-7 of 13 candidates
//   * Batcher merges + two-sorted-array split-formula selection
// ---------------------------------------------------------------------------

#define PCEX(a, b)                         \
    do {                                   \
        __half2 _mn = __hmin2((a), (b));   \
        (b) = __hmax2((a), (b));           \
        (a) = _mn;                         \
    } while (0)

// Optimal 9-comparator sorting network for 5 elements (Knuth).
__device__ __forceinline__ void sort5p(__half2& v0, __half2& v1, __half2& v2,
                                       __half2& v3, __half2& v4) {
    PCEX(v0, v1); PCEX(v3, v4); PCEX(v2, v4); PCEX(v2, v3); PCEX(v0, v3);
    PCEX(v0, v2); PCEX(v1, v4); PCEX(v1, v3); PCEX(v1, v2);
}

// symmetric reflect for pad<=2:  -1 -> 0, -2 -> 1, N -> N-1, N+1 -> N-2
__device__ __forceinline__ int refl(int i, int n) {
    i = (i < 0) ? (-1 - i) : i;
    i = (i >= n) ? (2 * n - 1 - i) : i;
    return i;
}

constexpr int IMG_H  = 512;
constexpr int IMG_W  = 512;
constexpr int PLANES = 16 * 3;            // B*C = 48
constexpr int PAIRS  = PLANES / 2;        // 24 packed plane-pairs
constexpr int TROWS  = 16;                // outputs per thread (vertical strip)
constexpr int STRIPS = IMG_H / TROWS;     // 32
constexpr int PSTRIDE = IMG_H * IMG_W;    // plane stride in floats

constexpr float SCALE    = 4096.0f;       // lift out of fp16-denormal range
constexpr float INV_SCALE = 1.0f / 4096.0f;

// load one (x,y) sample from both planes, scale, pack to half2
__device__ __forceinline__ __half2 ldpk(const float* rowA, int xo) {
    float a = __ldg(rowA + xo) * SCALE;
    float b = __ldg(rowA + xo + PSTRIDE) * SCALE;
    return __floats2half2_rn(a, b);
}

__global__ void __launch_bounds__(128)
median5x5_kernel(const float* __restrict__ src, float* __restrict__ dst) {
    const int tid   = blockIdx.x * blockDim.x + threadIdx.x;
    const int x     = tid & (IMG_W - 1);
    const int rest  = tid >> 9;                 // / 512
    const int strip = rest & (STRIPS - 1);      // % 32
    const int pair  = rest >> 5;                // / 32
    if (pair >= PAIRS) return;

    const float* sA = src + (size_t)(2 * pair) * PSTRIDE;     // plane 2p
    float*       dA = dst + (size_t)(2 * pair) * PSTRIDE;

    const int xm2 = refl(x - 2, IMG_W);
    const int xm1 = refl(x - 1, IMG_W);
    const int xp1 = refl(x + 1, IMG_W);
    const int xp2 = refl(x + 2, IMG_W);
    const int y0  = strip * TROWS;

    // Ring of 5 sorted horizontal windows, packed over the two planes.
    __half2 r[5][5];

    #pragma unroll
    for (int i = 0; i < 4; i++) {
        const int yy = refl(y0 - 2 + i, IMG_H);
        const float* rowA = sA + yy * IMG_W;
        r[i][0] = ldpk(rowA, xm2);
        r[i][1] = ldpk(rowA, xm1);
        r[i][2] = ldpk(rowA, x);
        r[i][3] = ldpk(rowA, xp1);
        r[i][4] = ldpk(rowA, xp2);
        sort5p(r[i][0], r[i][1], r[i][2], r[i][3], r[i][4]);
    }

    #pragma unroll
    for (int t = 0; t < TROWS; t++) {
        const int slot = (t + 4) % 5;   // compile-time constant per unrolled iter
        {
            const int yy = refl(y0 + t + 2, IMG_H);
            const float* rowA = sA + yy * IMG_W;
            r[slot][0] = ldpk(rowA, xm2);
            r[slot][1] = ldpk(rowA, xm1);
            r[slot][2] = ldpk(rowA, x);
            r[slot][3] = ldpk(rowA, xp1);
            r[slot][4] = ldpk(rowA, xp2);
            sort5p(r[slot][0], r[slot][1], r[slot][2], r[slot][3], r[slot][4]);
        }

        // ---- column sorts -> doubly sorted 5x5 matrix -------------------
        __half2 a0 = r[0][0], a1 = r[1][0], a2 = r[2][0], a3 = r[3][0], a4 = r[4][0];
        __half2 b0 = r[0][1], b1 = r[1][1], b2 = r[2][1], b3 = r[3][1], b4 = r[4][1];
        __half2 c0 = r[0][2], c1 = r[1][2], c2 = r[2][2], c3 = r[3][2], c4 = r[4][2];
        __half2 d0 = r[0][3], d1 = r[1][3], d2 = r[2][3], d3 = r[3][3], d4 = r[4][3];
        __half2 e0 = r[0][4], e1 = r[1][4], e2 = r[2][4], e3 = r[3][4], e4 = r[4][4];
        sort5p(a0, a1, a2, a3, a4);
        sort5p(b0, b1, b2, b3, b4);
        sort5p(c0, c1, c2, c3, c4);
        sort5p(d0, d1, d2, d3, d4);
        sort5p(e0, e1, e2, e3, e4);
        // Unused order statistics are dead; ptxas DCEs their producing ops.
        (void)a0; (void)a1; (void)a2; (void)b0; (void)b1; (void)c0; (void)c4;
        (void)d3; (void)d4; (void)e2; (void)e3; (void)e4;

        // 13 median candidates in 5 sorted chains (rows of the doubly-sorted
        // matrix): R1=(d0,e0) R2=(c1,d1,e1) R3=(b2,c2,d2) R4=(a3,b3,c3) R5=(a4,b4)
        // median(25) = rank-7 of these 13.

        // U = batcher_merge(R1(2), R2(3)) -> sorted 5
        __half2 s0 = __hmin2(d0, c1), t0 = __hmax2(d0, c1);
        __half2 v1 = __hmin2(t0, e1), v2 = __hmax2(t0, e1);
        __half2 w0 = __hmin2(e0, d1), w1 = __hmax2(e0, d1);
        __half2 U0 = s0;
        __half2 U1 = __hmin2(v1, w0), U2 = __hmax2(v1, w0);
        __half2 U3 = __hmin2(v2, w1), U4 = __hmax2(v2, w1);

        // V = batcher_merge(R4(3), R5(2)) -> sorted 5
        __half2 m0 = __hmin2(a3, a4), h0 = __hmax2(a3, a4);
        __half2 o1 = __hmin2(h0, c3), o2 = __hmax2(h0, c3);
        __half2 p0 = __hmin2(b3, b4), p1 = __hmax2(b3, b4);
        __half2 V0 = m0;
        __half2 V1 = __hmin2(o1, p0), V2 = __hmax2(o1, p0);
        __half2 V3 = __hmin2(o2, p1), V4 = __hmax2(o2, p1);

        // W = batcher_merge(U(5), R3(3)) -> sorted 8 (only W1..W6 needed)
        //   odd lanes: merge((U0,U2,U4), (b2,d2))
        __half2 mm  = __hmin2(U0, b2), hh  = __hmax2(U0, b2);
        __half2 oo1 = __hmin2(hh, U4), oo2 = __hmax2(hh, U4);
        __half2 qq0 = __hmin2(U2, d2), qq1 = __hmax2(U2, d2);
        __half2 O1 = __hmin2(oo1, qq0), O2 = __hmax2(oo1, qq0);
        __half2 O3 = __hmin2(oo2, qq1), O4 = __hmax2(oo2, qq1);
        (void)mm; (void)O4;  // W0 / W7 are dead
        //   even lanes: merge((U1,U3), (c2))
        __half2 m2 = __hmin2(U1, c2), h2 = __hmax2(U1, c2);
        __half2 E0 = m2;
        __half2 E1 = __hmin2(h2, U3), E2 = __hmax2(h2, U3);
        //   combine
        __half2 W1 = __hmin2(O1, E0), W2 = __hmax2(O1, E0);
        __half2 W3 = __hmin2(O2, E1), W4 = __hmax2(O2, E1);
        __half2 W5 = __hmin2(O3, E2), W6 = __hmax2(O3, E2);

        // rank-7 of union(W sorted 8, V sorted 5):
        //   min over i+j=7 of max(W[i-1], V[j-1])
        __half2 med = W6;
        med = __hmin2(med, __hmax2(W1, V4));
        med = __hmin2(med, __hmax2(W2, V3));
        med = __hmin2(med, __hmax2(W3, V2));
        med = __hmin2(med, __hmax2(W4, V1));
        med = __hmin2(med, __hmax2(W5, V0));

        const float mA = __low2float(med)  * INV_SCALE;
        const float mB = __high2float(med) * INV_SCALE;
        dA[(y0 + t) * IMG_W + x]           = mA;
        dA[(y0 + t) * IMG_W + x + PSTRIDE] = mB;
    }
}

extern "C" void kernel_launch(void* const* d_in, const int* in_sizes, int n_in,
                              void* d_out, int out_size) {
    (void)in_sizes; (void)n_in; (void)out_size;
    const float* src = (const float*)d_in[0];
    float*       dst = (float*)d_out;

    const int total_threads = PAIRS * IMG_W * STRIPS;   // 393216
    const int block = 128;
    const int grid  = total_threads / block;            // 3072
    median5x5_kernel<<<grid, block>>>(src, dst);
}